// round 15
// baseline (speedup 1.0000x reference)
#include <cuda_runtime.h>
#include <cuda_fp16.h>
#include <cstdint>

// Problem constants
#define N_  10000
#define K_  32
#define M_  (N_ * K_)      // 320000
#define H_  128

// ---------------- scratch (device globals) ------------------------------------
__device__ float S_nh [N_ * H_];
__device__ float S_c  [N_ * H_];
__device__ float S_nf1[N_ * H_];
__device__ float S_big[M_ * 384];
__device__ float S_w  [139264];          // transposed half weights

__device__ __forceinline__ float gelu_t(float x) {
    float x3 = x * x * x;
    return 0.5f * x * (1.f + tanhf(0.7978845608028654f * (x + 0.044715f * x3)));
}

// ---------------- f32 -> f16 copy ----------------------------------------------
__global__ void __launch_bounds__(256) half_kernel(
    const float* __restrict__ src, __half* __restrict__ dst, long n4)
{
    long i = (long)blockIdx.x * 256 + threadIdx.x;
    if (i >= n4) return;
    float4 v = ((const float4*)src)[i];
    ((__half2*)dst)[i * 2 + 0] = __floats2half2_rn(v.x, v.y);
    ((__half2*)dst)[i * 2 + 1] = __floats2half2_rn(v.z, v.w);
}

// ---------------- transpose + halve: src[K][N] -> dst[N][K] ----------------------
__global__ void __launch_bounds__(256) transpose_half(
    const float* __restrict__ src, __half* __restrict__ dst, int Krows, int Ncols)
{
    __shared__ float tile[32][33];
    int bx = blockIdx.x * 32, by = blockIdx.y * 32;
    int x = threadIdx.x & 31, y4 = threadIdx.x >> 5;
#pragma unroll
    for (int j = 0; j < 4; j++) {
        int r = by + y4 + j * 8;
        if (r < Krows && bx + x < Ncols)
            tile[y4 + j * 8][x] = src[(long)r * Ncols + bx + x];
    }
    __syncthreads();
#pragma unroll
    for (int j = 0; j < 4; j++) {
        int n = bx + y4 + j * 8;
        if (n < Ncols && by + x < Krows)
            dst[(long)n * Krows + by + x] = __float2half_rn(tile[x][y4 + j * 8]);
    }
}

// ---------------- layernorm: warp-per-row (mode: 0=f32 out, 1=f16 out) -----------
__global__ void __launch_bounds__(256) ln_kernel(
    const float* __restrict__ x, const float* __restrict__ g,
    const float* __restrict__ b, void* __restrict__ y, int mode, int nrows)
{
    int row  = blockIdx.x * 8 + (threadIdx.x >> 5);
    if (row >= nrows) return;
    int lane = threadIdx.x & 31;
    long base = (long)row * 128 + lane * 4;
    float4 v = *(const float4*)(x + base);
    float s  = v.x + v.y + v.z + v.w;
    float s2 = v.x*v.x + v.y*v.y + v.z*v.z + v.w*v.w;
#pragma unroll
    for (int o = 16; o; o >>= 1) {
        s  += __shfl_xor_sync(0xffffffffu, s,  o);
        s2 += __shfl_xor_sync(0xffffffffu, s2, o);
    }
    float mean = s * (1.f / 128.f);
    float var  = s2 * (1.f / 128.f) - mean * mean;
    float r = rsqrtf(var + 1e-5f);
    float4 gv = *(const float4*)(g + lane * 4);
    float4 bv = *(const float4*)(b + lane * 4);
    float o0 = (v.x - mean) * r * gv.x + bv.x;
    float o1 = (v.y - mean) * r * gv.y + bv.y;
    float o2 = (v.z - mean) * r * gv.z + bv.z;
    float o3 = (v.w - mean) * r * gv.w + bv.w;
    if (mode) {
        __half2 h0 = __floats2half2_rn(o0, o1);
        __half2 h1 = __floats2half2_rn(o2, o3);
        uint2 pk = make_uint2(*(uint32_t*)&h0, *(uint32_t*)&h1);
        *(uint2*)((__half*)y + base) = pk;
    } else {
        *(float4*)((float*)y + base) = make_float4(o0, o1, o2, o3);
    }
}

// ---------------- pipelined fp16 tensor GEMM (R5/R8-proven, unchanged) -----------
#define BK 32
#define AS_BYTES 10240
#define WS_OFF   20480
#define GEMM_SMEM 40960

__device__ __forceinline__ void cp16(uint32_t dst, const void* src, int sz) {
    asm volatile("cp.async.cg.shared.global [%0], [%1], 16, %2;"
                 :: "r"(dst), "l"(src), "r"(sz));
}

__global__ void __launch_bounds__(256, 2) gemm_h(
    const __half* __restrict__ A,  int kdA,
    const __half* __restrict__ A2, int kdA2,
    const __half* __restrict__ Wt, const __half* __restrict__ Wt2,
    const float* __restrict__ bias,
    const int*   __restrict__ gather,
    const float* __restrict__ rowvec, int rowdiv,
    const float* __restrict__ resid,
    void* __restrict__ out, float* __restrict__ out2,
    int M, int ncols, int flags)
{
    extern __shared__ __half smh[];
    uint32_t smb = (uint32_t)__cvta_generic_to_shared(smh);

    int tid  = threadIdx.x;
    int lane = tid & 31;
    int wid  = tid >> 5;
    int warp_m = wid >> 2;
    int warp_n = wid & 3;
    int qr = lane >> 2;
    int qc = lane & 3;
    int row0 = blockIdx.x * 128;
    int cb   = blockIdx.y * 128;

    int kc = tid & 3;
    int lrow0 = tid >> 2;
    long arow_[2]; int pr_[2];
#pragma unroll
    for (int i = 0; i < 2; i++) {
        int gr = row0 + lrow0 + 64 * i;
        pr_[i] = (gr < M) ? 16 : 0;
        arow_[i] = (gr < M) ? (gather ? (long)gather[gr] : (long)gr) : 0;
    }
    int t1 = kdA / BK;
    int nt = t1 + (A2 ? kdA2 / BK : 0);

#define ISSUE(T) do {                                                           \
        int _t = (T); int _p = (_t >= t1);                                      \
        const __half* _Ap = _p ? A2 : A;                                        \
        const __half* _Wp = _p ? Wt2 : Wt;                                      \
        int _kd = _p ? kdA2 : kdA;                                              \
        int _k0 = (_p ? _t - t1 : _t) * BK;                                     \
        uint32_t _ab = smb + (_t & 1) * AS_BYTES;                               \
        uint32_t _wb = smb + WS_OFF + (_t & 1) * AS_BYTES;                      \
        _Pragma("unroll")                                                       \
        for (int _i = 0; _i < 2; _i++)                                          \
            cp16(_ab + (lrow0 + 64 * _i) * 80 + kc * 16,                        \
                 _Ap + arow_[_i] * _kd + _k0 + kc * 8, pr_[_i]);                \
        _Pragma("unroll")                                                       \
        for (int _i = 0; _i < 2; _i++)                                          \
            cp16(_wb + (lrow0 + 64 * _i) * 80 + kc * 16,                        \
                 _Wp + (long)(cb + lrow0 + 64 * _i) * _kd + _k0 + kc * 8, 16);  \
        asm volatile("cp.async.commit_group;" ::: "memory");                    \
    } while (0)

    float acc[4][4][4];
#pragma unroll
    for (int i = 0; i < 4; i++)
#pragma unroll
        for (int j = 0; j < 4; j++)
#pragma unroll
            for (int c = 0; c < 4; c++) acc[i][j][c] = 0.f;

    ISSUE(0);
    for (int t = 0; t < nt; t++) {
        int cur = t & 1;
        if (t + 1 < nt) {
            ISSUE(t + 1);
            asm volatile("cp.async.wait_group 1;" ::: "memory");
        } else {
            asm volatile("cp.async.wait_group 0;" ::: "memory");
        }
        __syncthreads();

        const __half* Asf = smh + cur * (AS_BYTES / 2) + (warp_m * 64) * 40;
        const __half* Wsf = smh + (WS_OFF / 2) + cur * (AS_BYTES / 2) + (warp_n * 32) * 40;
#pragma unroll
        for (int ks = 0; ks < 2; ks++) {
            int k16 = ks * 16;
            uint32_t af[4][4];
#pragma unroll
            for (int mt = 0; mt < 4; mt++) {
                const __half* p = Asf + (mt * 16 + qr) * 40 + k16 + qc * 2;
                af[mt][0] = *(const uint32_t*)(p);
                af[mt][1] = *(const uint32_t*)(p + 8 * 40);
                af[mt][2] = *(const uint32_t*)(p + 8);
                af[mt][3] = *(const uint32_t*)(p + 8 * 40 + 8);
            }
            uint32_t bf[4][2];
#pragma unroll
            for (int nt2 = 0; nt2 < 4; nt2++) {
                const __half* p = Wsf + (nt2 * 8 + qr) * 40 + k16 + qc * 2;
                bf[nt2][0] = *(const uint32_t*)(p);
                bf[nt2][1] = *(const uint32_t*)(p + 8);
            }
#pragma unroll
            for (int mt = 0; mt < 4; mt++)
#pragma unroll
                for (int nt2 = 0; nt2 < 4; nt2++) {
                    asm volatile(
                        "mma.sync.aligned.m16n8k16.row.col.f32.f16.f16.f32 "
                        "{%0,%1,%2,%3}, {%4,%5,%6,%7}, {%8,%9}, {%0,%1,%2,%3};"
                        : "+f"(acc[mt][nt2][0]), "+f"(acc[mt][nt2][1]),
                          "+f"(acc[mt][nt2][2]), "+f"(acc[mt][nt2][3])
                        : "r"(af[mt][0]), "r"(af[mt][1]),
                          "r"(af[mt][2]), "r"(af[mt][3]),
                          "r"(bf[nt2][0]), "r"(bf[nt2][1]));
                }
        }
        __syncthreads();
    }
#undef ISSUE

    int gelu = flags & 1, halfout = flags & 2;
#pragma unroll
    for (int mt = 0; mt < 4; mt++) {
#pragma unroll
        for (int hh = 0; hh < 2; hh++) {
            int gr = row0 + warp_m * 64 + mt * 16 + hh * 8 + qr;
            if (gr >= M) continue;
            const float* rv = rowvec ? rowvec + (long)(gr / rowdiv) * 128 : nullptr;
#pragma unroll
            for (int nt2 = 0; nt2 < 4; nt2++) {
                int c = cb + warp_n * 32 + nt2 * 8 + qc * 2;
                float v0 = acc[mt][nt2][hh * 2 + 0];
                float v1 = acc[mt][nt2][hh * 2 + 1];
                if (bias) { v0 += bias[c];  v1 += bias[c + 1]; }
                if (rv)   { v0 += rv[c];    v1 += rv[c + 1]; }
                if (gelu) { v0 = gelu_t(v0); v1 = gelu_t(v1); }
                long oidx = (long)gr * ncols + c;
                if (halfout) {
                    *(__half2*)((__half*)out + oidx) = __floats2half2_rn(v0, v1);
                } else {
                    if (out2) *(float2*)(out2 + oidx) = make_float2(v0, v1);
                    if (resid) {
                        float2 r2 = *(const float2*)(resid + oidx);
                        v0 += r2.x; v1 += r2.y;
                    }
                    *(float2*)((float*)out + oidx) = make_float2(v0, v1);
                }
            }
        }
    }
}

// ---------------- fused edge pipeline: msg chain + attention + out-proj ----------
// Per CTA: 128 edge rows = 4 whole nodes. 512 threads, 4x4 warp grid.
#define MSG_SMEM 147456  // Ea/Nh/Eh 3*34816 + Wbuf 40960 + sAgg 2048

__device__ __forceinline__ void cvt16(float* o, const __half* p) {
    uint4 a = *(const uint4*)p, b = *(const uint4*)(p + 8);
    const __half2* ha = (const __half2*)&a;
    const __half2* hb = (const __half2*)&b;
#pragma unroll
    for (int i = 0; i < 4; i++) {
        float2 f = __half22float2(ha[i]);
        o[i * 2] = f.x; o[i * 2 + 1] = f.y;
    }
#pragma unroll
    for (int i = 0; i < 4; i++) {
        float2 f = __half22float2(hb[i]);
        o[8 + i * 2] = f.x; o[8 + i * 2 + 1] = f.y;
    }
}

__global__ void __launch_bounds__(512, 1) fused_edge(
    const __half* __restrict__ ea, const __half* __restrict__ nh,
    const float* __restrict__ center, const int* __restrict__ nbrs,
    const __half* __restrict__ We,  const float* __restrict__ b_e,
    const __half* __restrict__ Wn,  const float* __restrict__ b_n,
    const __half* __restrict__ WmE, const __half* __restrict__ WmN,
    const float* __restrict__ b_m,
    const __half* __restrict__ Wq,  const float* __restrict__ b_q,
    const __half* __restrict__ Wo,  const float* __restrict__ b_o,
    const int* __restrict__ num_valid,
    const float* __restrict__ edge_feat, const float* __restrict__ node_feat,
    float* __restrict__ out_edge, float* __restrict__ node1)
{
    extern __shared__ __half sm[];
    __half* Ea = sm;                  // [128][136]  Ea -> Msg -> V
    __half* Nh = sm + 17408;          //             Nh -> K
    __half* Eh = sm + 34816;          //             Eh -> Q -> ctx
    uint32_t wb = (uint32_t)__cvta_generic_to_shared(sm + 52224);  // 4 x 10240 B
    float* sAgg = (float*)(sm + 72704);                            // [4][128]
    uint32_t smb = (uint32_t)__cvta_generic_to_shared(sm);

    int tid = threadIdx.x, lane = tid & 31, wid = tid >> 5;
    int row0 = blockIdx.x * 128;
    int node0 = row0 >> 5;            // first of 4 nodes in this CTA
    int warp_m = wid >> 2, warp_n = wid & 3;
    int qr = lane >> 2, qc = lane & 3;
    int kc = tid & 3, lrow = tid >> 2;

    if (tid < 512) sAgg[tid] = 0.f;

    // ---- input loads: Ea rows + gathered Nh rows (one commit group) ----
    {
        long erow = (long)(row0 + lrow) * 128;
        long nrow = (long)nbrs[row0 + lrow] * 128;
#pragma unroll
        for (int i = 0; i < 4; i++) {
            int c16 = kc + 4 * i;
            cp16(smb + lrow * 272 + c16 * 16, ea + erow + c16 * 8, 16);
            cp16(smb + 17408 * 2 + lrow * 272 + c16 * 16, nh + nrow + c16 * 8, 16);
        }
        asm volatile("cp.async.commit_group;" ::: "memory");
    }

#define WLOADF(Wp, kd, nbase, k0base) do {                                       \
        _Pragma("unroll")                                                        \
        for (int _s = 0; _s < 4; _s++)                                           \
            cp16(wb + _s * 10240 + lrow * 80 + kc * 16,                          \
                 (Wp) + (long)((nbase) + lrow) * (kd) + (k0base) + _s * 32 + kc * 8, 16); \
        asm volatile("cp.async.commit_group;" ::: "memory");                     \
        asm volatile("cp.async.wait_group 0;" ::: "memory");                     \
        __syncthreads();                                                         \
    } while (0)

#define FRAG_MMA(Abase, ACC, T) do {                                             \
        const __half* _Ws = sm + 52224 + (T) * 5120 + (warp_n * 32) * 40;        \
        _Pragma("unroll")                                                        \
        for (int ks = 0; ks < 2; ks++) {                                         \
            int k16 = (T) * 32 + ks * 16;                                        \
            uint32_t af[2][4];                                                   \
            _Pragma("unroll")                                                    \
            for (int mt = 0; mt < 2; mt++) {                                     \
                const __half* p = (Abase) + (warp_m * 32 + mt * 16 + qr) * 136   \
                                  + k16 + qc * 2;                                \
                af[mt][0] = *(const uint32_t*)(p);                               \
                af[mt][1] = *(const uint32_t*)(p + 8 * 136);                     \
                af[mt][2] = *(const uint32_t*)(p + 8);                           \
                af[mt][3] = *(const uint32_t*)(p + 8 * 136 + 8);                 \
            }                                                                    \
            uint32_t bf[4][2];                                                   \
            _Pragma("unroll")                                                    \
            for (int nt2 = 0; nt2 < 4; nt2++) {                                  \
                const __half* p = _Ws + (nt2 * 8 + qr) * 40 + ks * 16 + qc * 2;  \
                bf[nt2][0] = *(const uint32_t*)(p);                              \
                bf[nt2][1] = *(const uint32_t*)(p + 8);                          \
            }                                                                    \
            _Pragma("unroll")                                                    \
            for (int mt = 0; mt < 2; mt++)                                       \
                _Pragma("unroll")                                                \
                for (int nt2 = 0; nt2 < 4; nt2++) {                              \
                    asm volatile(                                                \
                        "mma.sync.aligned.m16n8k16.row.col.f32.f16.f16.f32 "     \
                        "{%0,%1,%2,%3}, {%4,%5,%6,%7}, {%8,%9}, {%0,%1,%2,%3};"  \
                        : "+f"((ACC)[mt][nt2][0]), "+f"((ACC)[mt][nt2][1]),      \
                          "+f"((ACC)[mt][nt2][2]), "+f"((ACC)[mt][nt2][3])       \
                        : "r"(af[mt][0]), "r"(af[mt][1]),                        \
                          "r"(af[mt][2]), "r"(af[mt][3]),                        \
                          "r"(bf[nt2][0]), "r"(bf[nt2][1]));                     \
                }                                                                \
        }                                                                        \
    } while (0)

#define ZACC(A) do {                                                             \
        _Pragma("unroll")                                                        \
        for (int i = 0; i < 2; i++)                                              \
            _Pragma("unroll")                                                    \
            for (int j = 0; j < 4; j++)                                          \
                _Pragma("unroll")                                                \
                for (int c = 0; c < 4; c++) (A)[i][j][c] = 0.f;                  \
    } while (0)

// epilogue helper: write acc (+bias vec b, optional gelu) as f16 into buffer B
#define EPI_H16(B, BIASP, GELU) do {                                             \
        _Pragma("unroll")                                                        \
        for (int mt = 0; mt < 2; mt++)                                           \
            _Pragma("unroll")                                                    \
            for (int hh = 0; hh < 2; hh++) {                                     \
                int lr = warp_m * 32 + mt * 16 + hh * 8 + qr;                    \
                _Pragma("unroll")                                                \
                for (int nt2 = 0; nt2 < 4; nt2++) {                              \
                    int c = warp_n * 32 + nt2 * 8 + qc * 2;                      \
                    float v0 = acc[mt][nt2][hh * 2 + 0] + (BIASP)[c];            \
                    float v1 = acc[mt][nt2][hh * 2 + 1] + (BIASP)[c + 1];        \
                    if (GELU) { v0 = gelu_t(v0); v1 = gelu_t(v1); }              \
                    *(__half2*)((B) + lr * 136 + c) = __floats2half2_rn(v0, v1); \
                }                                                                \
            }                                                                    \
    } while (0)

    float acc[2][4][4];

    // ===== Phase 1: Eh = gelu(Ea @ We + b_e) =====
    ZACC(acc);
    WLOADF(We, 128, 0, 0);
#pragma unroll
    for (int t = 0; t < 4; t++) FRAG_MMA(Ea, acc, t);
    __syncthreads();
    EPI_H16(Eh, b_e, 1);

    // ===== Phase 2: Nh <- gelu(Nh @ Wn + center + b_n) (in place) =====
    ZACC(acc);
    WLOADF(Wn, 128, 0, 0);
#pragma unroll
    for (int t = 0; t < 4; t++) FRAG_MMA(Nh, acc, t);
    __syncthreads();
#pragma unroll
    for (int mt = 0; mt < 2; mt++)
#pragma unroll
        for (int hh = 0; hh < 2; hh++) {
            int lr = warp_m * 32 + mt * 16 + hh * 8 + qr;
            const float* cv = center + (long)((row0 + lr) >> 5) * 128;
#pragma unroll
            for (int nt2 = 0; nt2 < 4; nt2++) {
                int c = warp_n * 32 + nt2 * 8 + qc * 2;
                float2 ctr = *(const float2*)(cv + c);
                *(__half2*)(Nh + lr * 136 + c) = __floats2half2_rn(
                    gelu_t(acc[mt][nt2][hh * 2 + 0] + ctr.x + b_n[c]),
                    gelu_t(acc[mt][nt2][hh * 2 + 1] + ctr.y + b_n[c + 1]));
            }
        }

    // ===== Phase 3: Msg = gelu(Eh@WmE + Nh@WmN + b_m) -> Ea =====
    ZACC(acc);
    WLOADF(WmE, 128, 0, 0);
#pragma unroll
    for (int t = 0; t < 4; t++) FRAG_MMA(Eh, acc, t);
    __syncthreads();
    WLOADF(WmN, 128, 0, 0);
#pragma unroll
    for (int t = 0; t < 4; t++) FRAG_MMA(Nh, acc, t);
    __syncthreads();
    EPI_H16(Ea, b_m, 1);

    // ===== Phase 4a: Q = Msg @ Wq[0:128] -> Eh =====
    ZACC(acc);
    WLOADF(Wq, 128, 0, 0);
#pragma unroll
    for (int t = 0; t < 4; t++) FRAG_MMA(Ea, acc, t);
    __syncthreads();
    EPI_H16(Eh, b_q, 0);

    // ===== Phase 4b: K = Msg @ Wq[128:256] -> Nh =====
    ZACC(acc);
    WLOADF(Wq, 128, 128, 0);
#pragma unroll
    for (int t = 0; t < 4; t++) FRAG_MMA(Ea, acc, t);
    __syncthreads();
    EPI_H16(Nh, b_q + 128, 0);

    // ===== Phase 4c: V = Msg @ Wq[256:384] -> Ea (after reads complete) =====
    ZACC(acc);
    WLOADF(Wq, 128, 256, 0);
#pragma unroll
    for (int t = 0; t < 4; t++) FRAG_MMA(Ea, acc, t);
    __syncthreads();                 // all Msg reads done -> safe to overwrite Ea
    EPI_H16(Ea, b_q + 256, 0);
    __syncthreads();                 // publish Q/K/V for attention

    // ===== Phase 5: attention (Q=Eh, K=Nh, V=Ea) -> ctx -> Eh =====
    int nv4[4];
#pragma unroll
    for (int i = 0; i < 4; i++) nv4[i] = num_valid[node0 + i];

    float ctxA[2][16];
#pragma unroll
    for (int half = 0; half < 2; half++) {
        int it = tid + half * 512;       // 0..1023 = 4 nodes x 8 heads x 32 q
        int node = it >> 8;
        int head = (it >> 5) & 7;
        int q    = it & 31;
        int nv   = nv4[node];
        int rbase = node * 32;
        int hc = head * 16;
        float qv[16];
        cvt16(qv, Eh + (rbase + q) * 136 + hc);
        float s[32];
#pragma unroll
        for (int j = 0; j < 32; j++) {
            float kv[16];
            cvt16(kv, Nh + (rbase + j) * 136 + hc);
            float a = 0.f;
#pragma unroll
            for (int d = 0; d < 16; d++) a += qv[d] * kv[d];
            s[j] = a * 0.25f;
        }
        float m = -1e30f;
#pragma unroll
        for (int j = 0; j < 32; j++) if (j < nv && s[j] > m) m = s[j];
        float sum = 0.f;
#pragma unroll
        for (int j = 0; j < 32; j++) {
            float p = (j < nv) ? __expf(s[j] - m) : 0.f;
            s[j] = p; sum += p;
        }
        float inv = 1.f / sum;
#pragma unroll
        for (int d = 0; d < 16; d++) ctxA[half][d] = 0.f;
#pragma unroll
        for (int j = 0; j < 32; j++) {
            float p = s[j] * inv;
            float vv[16];
            cvt16(vv, Ea + (rbase + j) * 136 + hc);
#pragma unroll
            for (int d = 0; d < 16; d++) ctxA[half][d] += p * vv[d];
        }
    }
    __syncthreads();                 // all Q reads done -> ctx can overwrite Eh
#pragma unroll
    for (int half = 0; half < 2; half++) {
        int it = tid + half * 512;
        int node = it >> 8, head = (it >> 5) & 7, q = it & 31;
        __half* cd = Eh + (node * 32 + q) * 136 + head * 16;
        uint4 o0, o1; __half2 h;
        h = __floats2half2_rn(ctxA[half][0],  ctxA[half][1]);  o0.x = *(uint32_t*)&h;
        h = __floats2half2_rn(ctxA[half][2],  ctxA[half][3]);  o0.y = *(uint32_t*)&h;
        h = __floats2half2_rn(ctxA[half][4],  ctxA[half][5]);  o0.z = *(uint32_t*)&h;
        h = __floats2half2_rn(ctxA[half][6],  ctxA[half][7]);  o0.w = *(uint32_t*)&h;
        h = __floats2half2_rn(ctxA[half][8],  ctxA[half][9]);  o1.x = *(uint32_t*)&h;
        h = __floats2half2_rn(ctxA[half][10], ctxA[half][11]); o1.y = *(uint32_t*)&h;
        h = __floats2half2_rn(ctxA[half][12], ctxA[half][13]); o1.z = *(uint32_t*)&h;
        h = __floats2half2_rn(ctxA[half][14], ctxA[half][15]); o1.w = *(uint32_t*)&h;
        *(uint4*)cd = o0;
        *(uint4*)(cd + 8) = o1;
    }

    // ===== Phase 6: edge_out = ctx @ Wo + b_o; residual + masked aggregation =====
    ZACC(acc);
    WLOADF(Wo, 128, 0, 0);           // sync publishes ctx too
#pragma unroll
    for (int t = 0; t < 4; t++) FRAG_MMA(Eh, acc, t);
#pragma unroll
    for (int mt = 0; mt < 2; mt++) {
#pragma unroll
        for (int hh = 0; hh < 2; hh++) {
            int lr = warp_m * 32 + mt * 16 + hh * 8 + qr;
            int node = lr >> 5, kk = lr & 31;
            bool valid = kk < nv4[node];
            long erow = (long)(row0 + lr) * 128;
#pragma unroll
            for (int nt2 = 0; nt2 < 4; nt2++) {
                int c = warp_n * 32 + nt2 * 8 + qc * 2;
                float v0 = acc[mt][nt2][hh * 2 + 0] + b_o[c];
                float v1 = acc[mt][nt2][hh * 2 + 1] + b_o[c + 1];
                float m0 = valid ? v0 : 0.f;
                float m1 = valid ? v1 : 0.f;
#pragma unroll
                for (int off = 4; off <= 16; off <<= 1) {
                    m0 += __shfl_xor_sync(0xffffffffu, m0, off);
                    m1 += __shfl_xor_sync(0xffffffffu, m1, off);
                }
                if (qr == 0) {
                    atomicAdd(&sAgg[node * 128 + c], m0);
                    atomicAdd(&sAgg[node * 128 + c + 1], m1);
                }
                float2 r2 = *(const float2*)(edge_feat + erow + c);
                *(float2*)(out_edge + erow + c) = make_float2(v0 + r2.x, v1 + r2.y);
            }
        }
    }
    __syncthreads();
    {
        int node = tid >> 7, c = tid & 127;
        long nidx = (long)(node0 + node) * 128 + c;
        node1[nidx] = sAgg[node * 128 + c] + node_feat[nidx];
    }
#undef ZACC
#undef FRAG_MMA
#undef WLOADF
#undef EPI_H16
}

// ---------------- fused FFN (512 threads, 4-stage weight preload, R14) -------------
#define FFN_SMEM 110592
__global__ void __launch_bounds__(512, 1) fused_ffn(
    const float* __restrict__ x, const float* __restrict__ gg, const float* __restrict__ bb,
    const __half* __restrict__ W1t, const float* __restrict__ b1,
    const __half* __restrict__ W2t, const float* __restrict__ b2,
    const float* __restrict__ resid, float* __restrict__ out, int Mtot)
{
    extern __shared__ __half shf[];
    __half* As = shf;
    __half* Hs = shf + 17408;
    uint32_t wb = (uint32_t)__cvta_generic_to_shared(shf + 34816);

    int tid = threadIdx.x, lane = tid & 31, wid = tid >> 5;
    int row0 = blockIdx.x * 128;
    int warp_m = wid >> 2, warp_n = wid & 3;
    int qr = lane >> 2, qc = lane & 3;
    int kc = tid & 3, lrow = tid >> 2;

    for (int r = wid; r < 128; r += 16) {
        int gr = row0 + r;
        uint2 pk = make_uint2(0u, 0u);
        if (gr < Mtot) {
            float4 v = *(const float4*)(x + (long)gr * 128 + lane * 4);
            float s  = v.x + v.y + v.z + v.w;
            float s2 = v.x*v.x + v.y*v.y + v.z*v.z + v.w*v.w;
#pragma unroll
            for (int o = 16; o; o >>= 1) {
                s  += __shfl_xor_sync(0xffffffffu, s,  o);
                s2 += __shfl_xor_sync(0xffffffffu, s2, o);
            }
            float mean = s * (1.f / 128.f);
            float var  = s2 * (1.f / 128.f) - mean * mean;
            float rs = rsqrtf(var + 1e-5f);
            float4 gv = *(const float4*)(gg + lane * 4);
            float4 bv = *(const float4*)(bb + lane * 4);
            __half2 h0 = __floats2half2_rn((v.x - mean) * rs * gv.x + bv.x,
                                           (v.y - mean) * rs * gv.y + bv.y);
            __half2 h1 = __floats2half2_rn((v.z - mean) * rs * gv.z + bv.z,
                                           (v.w - mean) * rs * gv.w + bv.w);
            pk = make_uint2(*(uint32_t*)&h0, *(uint32_t*)&h1);
        }
        *(uint2*)(As + r * 136 + lane * 4) = pk;
    }

#define WLOADF(Wp, kd, nbase, k0base) do {                                       \
        _Pragma("unroll")                                                        \
        for (int _s = 0; _s < 4; _s++)                                           \
            cp16(wb + _s * 10240 + lrow * 80 + kc * 16,                          \
                 (Wp) + (long)((nbase) + lrow) * (kd) + (k0base) + _s * 32 + kc * 8, 16); \
        asm volatile("cp.async.commit_group;" ::: "memory");                     \
        asm volatile("cp.async.wait_group 0;" ::: "memory");                     \
        __syncthreads();                                                         \
    } while (0)

#define FRAG_MMA(Abase, ACC, T) do {                                             \
        const __half* _Ws = (const __half*)(shf + 34816) + (T) * 5120            \
                            + (warp_n * 32) * 40;                                \
        _Pragma("unroll")                                                        \
        for (int ks = 0; ks < 2; ks++) {                                         \
            int k16 = (T) * 32 + ks * 16;                                        \
            uint32_t af[2][4];                                                   \
            _Pragma("unroll")                                                    \
            for (int mt = 0; mt < 2; mt++) {                                     \
                const __half* p = (Abase) + (warp_m * 32 + mt * 16 + qr) * 136   \
                                  + k16 + qc * 2;                                \
                af[mt][0] = *(const uint32_t*)(p);                               \
                af[mt][1] = *(const uint32_t*)(p + 8 * 136);                     \
                af[mt][2] = *(const uint32_t*)(p + 8);                           \
                af[mt][3] = *(const uint32_t*)(p + 8 * 136 + 8);                 \
            }                                                                    \
            uint32_t bf[4][2];                                                   \
            _Pragma("unroll")                                                    \
            for (int nt2 = 0; nt2 < 4; nt2++) {                                  \
                const __half* p = _Ws + (nt2 * 8 + qr) * 40 + ks * 16 + qc * 2;  \
                bf[nt2][0] = *(const uint32_t*)(p);                              \
                bf[nt2][1] = *(const uint32_t*)(p + 8);                          \
            }                                                                    \
            _Pragma("unroll")                                                    \
            for (int mt = 0; mt < 2; mt++)                                       \
                _Pragma("unroll")                                                \
                for (int nt2 = 0; nt2 < 4; nt2++) {                              \
                    asm volatile(                                                \
                        "mma.sync.aligned.m16n8k16.row.col.f32.f16.f16.f32 "     \
                        "{%0,%1,%2,%3}, {%4,%5,%6,%7}, {%8,%9}, {%0,%1,%2,%3};"  \
                        : "+f"((ACC)[mt][nt2][0]), "+f"((ACC)[mt][nt2][1]),      \
                          "+f"((ACC)[mt][nt2][2]), "+f"((ACC)[mt][nt2][3])       \
                        : "r"(af[mt][0]), "r"(af[mt][1]),                        \
                          "r"(af[mt][2]), "r"(af[mt][3]),                        \
                          "r"(bf[nt2][0]), "r"(bf[nt2][1]));                     \
                }                                                                \
        }                                                                        \
    } while (0)

    float acc2[2][4][4];
#pragma unroll
    for (int i = 0; i < 2; i++)
#pragma unroll
        for (int j = 0; j < 4; j++)
#pragma unroll
            for (int c = 0; c < 4; c++) acc2[i][j][c] = 0.f;

    for (int nh = 0; nh < 2; nh++) {
        float acc1[2][4][4];
#pragma unroll
        for (int i = 0; i < 2; i++)
#pragma unroll
            for (int j = 0; j < 4; j++)
#pragma unroll
                for (int c = 0; c < 4; c++) acc1[i][j][c] = 0.f;

        WLOADF(W1t, 128, nh * 128, 0);
#pragma unroll
        for (int t = 0; t < 4; t++) FRAG_MMA(As, acc1, t);
        __syncthreads();
#pragma unroll
        for (int mt = 0; mt < 2; mt++) {
#pragma unroll
            for (int hh = 0; hh < 2; hh++) {
                int lr = warp_m * 32 + mt * 16 + hh * 8 + qr;
#pragma unroll
                for (int nt2 = 0; nt2 < 4; nt2++) {
                    int c = warp_n * 32 + nt2 * 8 + qc * 2;
                    float v0 = gelu_t(acc1[mt][nt2][hh * 2 + 0] + b1[nh * 128 + c]);
                    float v1 = gelu_t(acc1[mt][nt2][hh * 2 + 1] + b1[nh * 128 + c + 1]);
                    *(__half2*)(Hs + lr * 136 + c) = __floats2half2_rn(v0, v1);
                }
            }
        }

        WLOADF(W2t, 256, 0, nh * 128);
#pragma unroll
        for (int t = 0; t < 4; t++) FRAG_MMA(Hs, acc2, t);
        __syncthreads();
    }
#undef FRAG_MMA
#undef WLOADF

#pragma unroll
    for (int mt = 0; mt < 2; mt++) {
#pragma unroll
        for (int hh = 0; hh < 2; hh++) {
            int gr = row0 + warp_m * 32 + mt * 16 + hh * 8 + qr;
            if (gr >= Mtot) continue;
#pragma unroll
            for (int nt2 = 0; nt2 < 4; nt2++) {
                int c = warp_n * 32 + nt2 * 8 + qc * 2;
                float v0 = acc2[mt][nt2][hh * 2 + 0] + b2[c];
                float v1 = acc2[mt][nt2][hh * 2 + 1] + b2[c + 1];
                long oidx = (long)gr * 128 + c;
                float2 r2 = *(const float2*)(resid + oidx);
                *(float2*)(out + oidx) = make_float2(v0 + r2.x, v1 + r2.y);
            }
        }
    }
}

// ---------------- driver -----------------------------------------------------------
static void launch_gemm(const __half* A, int kdA, const __half* A2, int kdA2,
                        const __half* Wt, const __half* Wt2, const float* bias,
                        const int* gather, const float* rowvec, int rowdiv,
                        const float* resid, void* out, float* out2,
                        int M, int ncols, int flags)
{
    dim3 g((M + 127) / 128, ncols / 128);
    gemm_h<<<g, 256, GEMM_SMEM>>>(A, kdA, A2, kdA2, Wt, Wt2, bias, gather,
                                  rowvec, rowdiv, resid, out, out2, M, ncols, flags);
}
static void launch_T(const float* src, __half* dst, int K, int N) {
    dim3 g((N + 31) / 32, (K + 31) / 32);
    transpose_half<<<g, 256>>>(src, dst, K, N);
}
static void launch_half(const float* src, __half* dst, long n) {
    long n4 = n / 4;
    half_kernel<<<(unsigned)((n4 + 255) / 256), 256>>>(src, dst, n4);
}
static void launch_ln(const float* x, const float* g, const float* b,
                      void* y, int mode, int nrows) {
    ln_kernel<<<(nrows + 7) / 8, 256>>>(x, g, b, y, mode, nrows);
}

extern "C" void kernel_launch(void* const* d_in, const int* in_sizes, int n_in,
                              void* d_out, int out_size)
{
    const float* node_features = (const float*)d_in[0];
    const float* edge_features = (const float*)d_in[1];
    const float* edge_attr     = (const float*)d_in[2];
    const int*   neighbor_list = (const int*)d_in[3];
    const int*   num_valid     = (const int*)d_in[4];
    const float* W_edge = (const float*)d_in[5];
    const float* b_edge = (const float*)d_in[6];
    const float* W_node = (const float*)d_in[7];
    const float* b_node = (const float*)d_in[8];
    const float* W_msg  = (const float*)d_in[9];
    const float* b_msg  = (const float*)d_in[10];
    const float* W_qkv  = (const float*)d_in[11];
    const float* b_qkv  = (const float*)d_in[12];
    const float* W_out  = (const float*)d_in[13];
    const float* b_out  = (const float*)d_in[14];
    const float* g_attn = (const float*)d_in[15];
    const float* be_attn= (const float*)d_in[16];
    const float* g_fn   = (const float*)d_in[17];
    const float* be_fn  = (const float*)d_in[18];
    const float* g_fe   = (const float*)d_in[19];
    const float* be_fe  = (const float*)d_in[20];
    const float* Wn1 = (const float*)d_in[21];
    const float* bn1 = (const float*)d_in[22];
    const float* Wn2 = (const float*)d_in[23];
    const float* bn2 = (const float*)d_in[24];
    const float* We1 = (const float*)d_in[25];
    const float* be1 = (const float*)d_in[26];
    const float* We2 = (const float*)d_in[27];
    const float* be2 = (const float*)d_in[28];

    float *s_nh, *s_c, *s_nf1, *s_big, *s_w;
    cudaGetSymbolAddress((void**)&s_nh,  S_nh);
    cudaGetSymbolAddress((void**)&s_c,   S_c);
    cudaGetSymbolAddress((void**)&s_nf1, S_nf1);
    cudaGetSymbolAddress((void**)&s_big, S_big);
    cudaGetSymbolAddress((void**)&s_w,   S_w);

    cudaFuncSetAttribute(fused_edge, cudaFuncAttributeMaxDynamicSharedMemorySize, MSG_SMEM);
    cudaFuncSetAttribute(fused_ffn,  cudaFuncAttributeMaxDynamicSharedMemorySize, FFN_SMEM);

    float* out_node = (float*)d_out;
    float* out_edge = out_node + (long)N_ * H_;

    __half* h_nh  = (__half*)s_nh;
    __half* h_ea  = (__half*)s_big;     // f16 edge_attr staging

    __half* wbase = (__half*)s_w;
    __half* tW_edge  = wbase;
    __half* tW_nodeC = wbase + 16384;
    __half* tW_nodeN = wbase + 32768;
    __half* tW_msgE  = wbase + 49152;
    __half* tW_msgN  = wbase + 65536;
    __half* tW_qkv   = wbase + 81920;
    __half* tW_out   = wbase + 131072;
    __half* tWn1     = wbase + 147456;
    __half* tWn2     = wbase + 180224;
    __half* tWe1     = wbase + 212992;
    __half* tWe2     = wbase + 245760;

    // 0) transpose+halve weights; halve edge_attr
    launch_T(W_edge,            tW_edge,  128, 128);
    launch_T(W_node,            tW_nodeC, 128, 128);
    launch_T(W_node + 128*128,  tW_nodeN, 128, 128);
    launch_T(W_msg,             tW_msgE,  128, 128);
    launch_T(W_msg + 128*128,   tW_msgN,  128, 128);
    launch_T(W_qkv,             tW_qkv,   128, 384);
    launch_T(W_out,             tW_out,   128, 128);
    launch_T(Wn1,               tWn1,     128, 256);
    launch_T(Wn2,               tWn2,     256, 128);
    launch_T(We1,               tWe1,     128, 256);
    launch_T(We2,               tWe2,     256, 128);
    launch_half(edge_attr, h_ea, (long)M_ * 128);

    // 1) node_hidden = LN(node_features) -> f16
    launch_ln(node_features, g_attn, be_attn, h_nh, 1, N_);
    // 2) center proj -> f32
    launch_gemm(h_nh, 128, nullptr, 0, tW_nodeC, nullptr, nullptr,
                nullptr, nullptr, 1, nullptr, s_c, nullptr, N_, 128, 0);
    // 3) fused edge pipeline: msg chain + attention + out-proj + residual + agg
    fused_edge<<<M_ / 128, 512, MSG_SMEM>>>(
        h_ea, h_nh, s_c, neighbor_list,
        tW_edge, b_edge, tW_nodeN, b_node,
        tW_msgE, tW_msgN, b_msg, tW_qkv, b_qkv,
        tW_out, b_out, num_valid,
        edge_features, node_features, out_edge, s_nf1);
    // 4) node FFN (fused)
    fused_ffn<<<(N_ + 127) / 128, 512, FFN_SMEM>>>(
        s_nf1, g_fn, be_fn, tWn1, bn1, tWn2, bn2, s_nf1, out_node, N_);
    // 5) edge FFN (fused; in-place over out_edge)
    fused_ffn<<<(M_ + 127) / 128, 512, FFN_SMEM>>>(
        out_edge, g_fe, be_fe, tWe1, be1, tWe2, be2, out_edge, out_edge, M_);
}

// round 16
// speedup vs baseline: 1.3946x; 1.3946x over previous
#include <cuda_runtime.h>
#include <cuda_fp16.h>
#include <cstdint>

// Problem constants
#define N_  10000
#define K_  32
#define M_  (N_ * K_)      // 320000
#define H_  128

// ---------------- scratch (device globals) ------------------------------------
__device__ float S_nh [N_ * H_];
__device__ float S_c  [N_ * H_];
__device__ float S_nf1[N_ * H_];
__device__ float S_big[M_ * 384];
__device__ float S_w  [139264];          // transposed half weights

__device__ __forceinline__ float gelu_t(float x) {
    float x3 = x * x * x;
    return 0.5f * x * (1.f + tanhf(0.7978845608028654f * (x + 0.044715f * x3)));
}

// ---------------- f32 -> f16 copy ----------------------------------------------
__global__ void __launch_bounds__(256) half_kernel(
    const float* __restrict__ src, __half* __restrict__ dst, long n4)
{
    long i = (long)blockIdx.x * 256 + threadIdx.x;
    if (i >= n4) return;
    float4 v = ((const float4*)src)[i];
    ((__half2*)dst)[i * 2 + 0] = __floats2half2_rn(v.x, v.y);
    ((__half2*)dst)[i * 2 + 1] = __floats2half2_rn(v.z, v.w);
}

// ---------------- transpose + halve: src[K][N] -> dst[N][K] ----------------------
__global__ void __launch_bounds__(256) transpose_half(
    const float* __restrict__ src, __half* __restrict__ dst, int Krows, int Ncols)
{
    __shared__ float tile[32][33];
    int bx = blockIdx.x * 32, by = blockIdx.y * 32;
    int x = threadIdx.x & 31, y4 = threadIdx.x >> 5;
#pragma unroll
    for (int j = 0; j < 4; j++) {
        int r = by + y4 + j * 8;
        if (r < Krows && bx + x < Ncols)
            tile[y4 + j * 8][x] = src[(long)r * Ncols + bx + x];
    }
    __syncthreads();
#pragma unroll
    for (int j = 0; j < 4; j++) {
        int n = bx + y4 + j * 8;
        if (n < Ncols && by + x < Krows)
            dst[(long)n * Krows + by + x] = __float2half_rn(tile[x][y4 + j * 8]);
    }
}

// ---------------- layernorm: warp-per-row (mode: 0=f32 out, 1=f16 out) -----------
__global__ void __launch_bounds__(256) ln_kernel(
    const float* __restrict__ x, const float* __restrict__ g,
    const float* __restrict__ b, void* __restrict__ y, int mode, int nrows)
{
    int row  = blockIdx.x * 8 + (threadIdx.x >> 5);
    if (row >= nrows) return;
    int lane = threadIdx.x & 31;
    long base = (long)row * 128 + lane * 4;
    float4 v = *(const float4*)(x + base);
    float s  = v.x + v.y + v.z + v.w;
    float s2 = v.x*v.x + v.y*v.y + v.z*v.z + v.w*v.w;
#pragma unroll
    for (int o = 16; o; o >>= 1) {
        s  += __shfl_xor_sync(0xffffffffu, s,  o);
        s2 += __shfl_xor_sync(0xffffffffu, s2, o);
    }
    float mean = s * (1.f / 128.f);
    float var  = s2 * (1.f / 128.f) - mean * mean;
    float r = rsqrtf(var + 1e-5f);
    float4 gv = *(const float4*)(g + lane * 4);
    float4 bv = *(const float4*)(b + lane * 4);
    float o0 = (v.x - mean) * r * gv.x + bv.x;
    float o1 = (v.y - mean) * r * gv.y + bv.y;
    float o2 = (v.z - mean) * r * gv.z + bv.z;
    float o3 = (v.w - mean) * r * gv.w + bv.w;
    if (mode) {
        __half2 h0 = __floats2half2_rn(o0, o1);
        __half2 h1 = __floats2half2_rn(o2, o3);
        uint2 pk = make_uint2(*(uint32_t*)&h0, *(uint32_t*)&h1);
        *(uint2*)((__half*)y + base) = pk;
    } else {
        *(float4*)((float*)y + base) = make_float4(o0, o1, o2, o3);
    }
}

// ---------------- pipelined fp16 tensor GEMM (R5/R8-proven, unchanged) -----------
#define BK 32
#define AS_BYTES 10240
#define WS_OFF   20480
#define GEMM_SMEM 40960

__device__ __forceinline__ void cp16(uint32_t dst, const void* src, int sz) {
    asm volatile("cp.async.cg.shared.global [%0], [%1], 16, %2;"
                 :: "r"(dst), "l"(src), "r"(sz));
}

__global__ void __launch_bounds__(256, 2) gemm_h(
    const __half* __restrict__ A,  int kdA,
    const __half* __restrict__ A2, int kdA2,
    const __half* __restrict__ Wt, const __half* __restrict__ Wt2,
    const float* __restrict__ bias,
    const int*   __restrict__ gather,
    const float* __restrict__ rowvec, int rowdiv,
    const float* __restrict__ resid,
    void* __restrict__ out, float* __restrict__ out2,
    int M, int ncols, int flags)
{
    extern __shared__ __half smh[];
    uint32_t smb = (uint32_t)__cvta_generic_to_shared(smh);

    int tid  = threadIdx.x;
    int lane = tid & 31;
    int wid  = tid >> 5;
    int warp_m = wid >> 2;
    int warp_n = wid & 3;
    int qr = lane >> 2;
    int qc = lane & 3;
    int row0 = blockIdx.x * 128;
    int cb   = blockIdx.y * 128;

    int kc = tid & 3;
    int lrow0 = tid >> 2;
    long arow_[2]; int pr_[2];
#pragma unroll
    for (int i = 0; i < 2; i++) {
        int gr = row0 + lrow0 + 64 * i;
        pr_[i] = (gr < M) ? 16 : 0;
        arow_[i] = (gr < M) ? (gather ? (long)gather[gr] : (long)gr) : 0;
    }
    int t1 = kdA / BK;
    int nt = t1 + (A2 ? kdA2 / BK : 0);

#define ISSUE(T) do {                                                           \
        int _t = (T); int _p = (_t >= t1);                                      \
        const __half* _Ap = _p ? A2 : A;                                        \
        const __half* _Wp = _p ? Wt2 : Wt;                                      \
        int _kd = _p ? kdA2 : kdA;                                              \
        int _k0 = (_p ? _t - t1 : _t) * BK;                                     \
        uint32_t _ab = smb + (_t & 1) * AS_BYTES;                               \
        uint32_t _wb = smb + WS_OFF + (_t & 1) * AS_BYTES;                      \
        _Pragma("unroll")                                                       \
        for (int _i = 0; _i < 2; _i++)                                          \
            cp16(_ab + (lrow0 + 64 * _i) * 80 + kc * 16,                        \
                 _Ap + arow_[_i] * _kd + _k0 + kc * 8, pr_[_i]);                \
        _Pragma("unroll")                                                       \
        for (int _i = 0; _i < 2; _i++)                                          \
            cp16(_wb + (lrow0 + 64 * _i) * 80 + kc * 16,                        \
                 _Wp + (long)(cb + lrow0 + 64 * _i) * _kd + _k0 + kc * 8, 16);  \
        asm volatile("cp.async.commit_group;" ::: "memory");                    \
    } while (0)

    float acc[4][4][4];
#pragma unroll
    for (int i = 0; i < 4; i++)
#pragma unroll
        for (int j = 0; j < 4; j++)
#pragma unroll
            for (int c = 0; c < 4; c++) acc[i][j][c] = 0.f;

    ISSUE(0);
    for (int t = 0; t < nt; t++) {
        int cur = t & 1;
        if (t + 1 < nt) {
            ISSUE(t + 1);
            asm volatile("cp.async.wait_group 1;" ::: "memory");
        } else {
            asm volatile("cp.async.wait_group 0;" ::: "memory");
        }
        __syncthreads();

        const __half* Asf = smh + cur * (AS_BYTES / 2) + (warp_m * 64) * 40;
        const __half* Wsf = smh + (WS_OFF / 2) + cur * (AS_BYTES / 2) + (warp_n * 32) * 40;
#pragma unroll
        for (int ks = 0; ks < 2; ks++) {
            int k16 = ks * 16;
            uint32_t af[4][4];
#pragma unroll
            for (int mt = 0; mt < 4; mt++) {
                const __half* p = Asf + (mt * 16 + qr) * 40 + k16 + qc * 2;
                af[mt][0] = *(const uint32_t*)(p);
                af[mt][1] = *(const uint32_t*)(p + 8 * 40);
                af[mt][2] = *(const uint32_t*)(p + 8);
                af[mt][3] = *(const uint32_t*)(p + 8 * 40 + 8);
            }
            uint32_t bf[4][2];
#pragma unroll
            for (int nt2 = 0; nt2 < 4; nt2++) {
                const __half* p = Wsf + (nt2 * 8 + qr) * 40 + k16 + qc * 2;
                bf[nt2][0] = *(const uint32_t*)(p);
                bf[nt2][1] = *(const uint32_t*)(p + 8);
            }
#pragma unroll
            for (int mt = 0; mt < 4; mt++)
#pragma unroll
                for (int nt2 = 0; nt2 < 4; nt2++) {
                    asm volatile(
                        "mma.sync.aligned.m16n8k16.row.col.f32.f16.f16.f32 "
                        "{%0,%1,%2,%3}, {%4,%5,%6,%7}, {%8,%9}, {%0,%1,%2,%3};"
                        : "+f"(acc[mt][nt2][0]), "+f"(acc[mt][nt2][1]),
                          "+f"(acc[mt][nt2][2]), "+f"(acc[mt][nt2][3])
                        : "r"(af[mt][0]), "r"(af[mt][1]),
                          "r"(af[mt][2]), "r"(af[mt][3]),
                          "r"(bf[nt2][0]), "r"(bf[nt2][1]));
                }
        }
        __syncthreads();
    }
#undef ISSUE

    int gelu = flags & 1, halfout = flags & 2;
#pragma unroll
    for (int mt = 0; mt < 4; mt++) {
#pragma unroll
        for (int hh = 0; hh < 2; hh++) {
            int gr = row0 + warp_m * 64 + mt * 16 + hh * 8 + qr;
            if (gr >= M) continue;
            const float* rv = rowvec ? rowvec + (long)(gr / rowdiv) * 128 : nullptr;
#pragma unroll
            for (int nt2 = 0; nt2 < 4; nt2++) {
                int c = cb + warp_n * 32 + nt2 * 8 + qc * 2;
                float v0 = acc[mt][nt2][hh * 2 + 0];
                float v1 = acc[mt][nt2][hh * 2 + 1];
                if (bias) { v0 += bias[c];  v1 += bias[c + 1]; }
                if (rv)   { v0 += rv[c];    v1 += rv[c + 1]; }
                if (gelu) { v0 = gelu_t(v0); v1 = gelu_t(v1); }
                long oidx = (long)gr * ncols + c;
                if (halfout) {
                    *(__half2*)((__half*)out + oidx) = __floats2half2_rn(v0, v1);
                } else {
                    if (out2) *(float2*)(out2 + oidx) = make_float2(v0, v1);
                    if (resid) {
                        float2 r2 = *(const float2*)(resid + oidx);
                        v0 += r2.x; v1 += r2.y;
                    }
                    *(float2*)((float*)out + oidx) = make_float2(v0, v1);
                }
            }
        }
    }
}

// ---------------- fused edge message chain (double-buffered weight preload) -------
// Per CTA: 128 edge rows. 512 threads, 4x4 warp grid.
#define MSG_SMEM 186368  // Ea/Nh/Eh 3*34816 + Wbuf 2*40960

__global__ void __launch_bounds__(512, 1) fused_msg(
    const __half* __restrict__ ea, const __half* __restrict__ nh,
    const float* __restrict__ center, const int* __restrict__ nbrs,
    const __half* __restrict__ We,  const float* __restrict__ b_e,
    const __half* __restrict__ Wn,  const float* __restrict__ b_n,
    const __half* __restrict__ WmE, const __half* __restrict__ WmN,
    const float* __restrict__ b_m,
    const __half* __restrict__ Wq,  const float* __restrict__ b_q,
    __half* __restrict__ qkv)
{
    extern __shared__ __half sm[];
    __half* Ea = sm;                  // [128][136]
    __half* Nh = sm + 17408;
    __half* Eh = sm + 34816;
    uint32_t wb = (uint32_t)__cvta_generic_to_shared(sm + 52224);  // 2 x 40960 B
    uint32_t smb = (uint32_t)__cvta_generic_to_shared(sm);

    int tid = threadIdx.x, lane = tid & 31, wid = tid >> 5;
    int row0 = blockIdx.x * 128;
    int warp_m = wid >> 2, warp_n = wid & 3;
    int qr = lane >> 2, qc = lane & 3;
    int kc = tid & 3, lrow = tid >> 2;

    // ---- input loads: Ea rows + gathered Nh rows (one commit group) ----
    {
        long erow = (long)(row0 + lrow) * 128;
        long nrow = (long)nbrs[row0 + lrow] * 128;
#pragma unroll
        for (int i = 0; i < 4; i++) {
            int c16 = kc + 4 * i;
            cp16(smb + lrow * 272 + c16 * 16, ea + erow + c16 * 8, 16);
            cp16(smb + 17408 * 2 + lrow * 272 + c16 * 16, nh + nrow + c16 * 8, 16);
        }
        asm volatile("cp.async.commit_group;" ::: "memory");
    }

// prefetch a full 128x128 weight into double-buffer slot S (no wait)
#define WPRE(Wp, kd, nbase, k0base, S) do {                                      \
        _Pragma("unroll")                                                        \
        for (int _s = 0; _s < 4; _s++)                                           \
            cp16(wb + (S) * 40960 + _s * 10240 + lrow * 80 + kc * 16,            \
                 (Wp) + (long)((nbase) + lrow) * (kd) + (k0base) + _s * 32 + kc * 8, 16); \
        asm volatile("cp.async.commit_group;" ::: "memory");                     \
    } while (0)
#define WWAIT1() do {                                                            \
        asm volatile("cp.async.wait_group 1;" ::: "memory");                     \
        __syncthreads();                                                         \
    } while (0)
#define WWAIT0() do {                                                            \
        asm volatile("cp.async.wait_group 0;" ::: "memory");                     \
        __syncthreads();                                                         \
    } while (0)

#define FRAG_MMA(Abase, ACC, T, S) do {                                          \
        const __half* _Ws = sm + 52224 + (S) * 20480 + (T) * 5120                \
                            + (warp_n * 32) * 40;                                \
        _Pragma("unroll")                                                        \
        for (int ks = 0; ks < 2; ks++) {                                         \
            int k16 = (T) * 32 + ks * 16;                                        \
            uint32_t af[2][4];                                                   \
            _Pragma("unroll")                                                    \
            for (int mt = 0; mt < 2; mt++) {                                     \
                const __half* p = (Abase) + (warp_m * 32 + mt * 16 + qr) * 136   \
                                  + k16 + qc * 2;                                \
                af[mt][0] = *(const uint32_t*)(p);                               \
                af[mt][1] = *(const uint32_t*)(p + 8 * 136);                     \
                af[mt][2] = *(const uint32_t*)(p + 8);                           \
                af[mt][3] = *(const uint32_t*)(p + 8 * 136 + 8);                 \
            }                                                                    \
            uint32_t bf[4][2];                                                   \
            _Pragma("unroll")                                                    \
            for (int nt2 = 0; nt2 < 4; nt2++) {                                  \
                const __half* p = _Ws + (nt2 * 8 + qr) * 40 + ks * 16 + qc * 2;  \
                bf[nt2][0] = *(const uint32_t*)(p);                              \
                bf[nt2][1] = *(const uint32_t*)(p + 8);                          \
            }                                                                    \
            _Pragma("unroll")                                                    \
            for (int mt = 0; mt < 2; mt++)                                       \
                _Pragma("unroll")                                                \
                for (int nt2 = 0; nt2 < 4; nt2++) {                              \
                    asm volatile(                                                \
                        "mma.sync.aligned.m16n8k16.row.col.f32.f16.f16.f32 "     \
                        "{%0,%1,%2,%3}, {%4,%5,%6,%7}, {%8,%9}, {%0,%1,%2,%3};"  \
                        : "+f"((ACC)[mt][nt2][0]), "+f"((ACC)[mt][nt2][1]),      \
                          "+f"((ACC)[mt][nt2][2]), "+f"((ACC)[mt][nt2][3])       \
                        : "r"(af[mt][0]), "r"(af[mt][1]),                        \
                          "r"(af[mt][2]), "r"(af[mt][3]),                        \
                          "r"(bf[nt2][0]), "r"(bf[nt2][1]));                     \
                }                                                                \
        }                                                                        \
    } while (0)

#define ZACC(A) do {                                                             \
        _Pragma("unroll")                                                        \
        for (int i = 0; i < 2; i++)                                              \
            _Pragma("unroll")                                                    \
            for (int j = 0; j < 4; j++)                                          \
                _Pragma("unroll")                                                \
                for (int c = 0; c < 4; c++) (A)[i][j][c] = 0.f;                  \
    } while (0)

    float acc[2][4][4];

    // prefetch chain: We(S0), Wn(S1), WmE(S0), WmN(S1), Wq0(S0), Wq1(S1), Wq2(S0)
    WPRE(We, 128, 0, 0, 0);

    // ===== Phase 1: Eh = gelu(Ea @ We + b_e)  [S0] =====
    ZACC(acc);
    WPRE(Wn, 128, 0, 0, 1);
    WWAIT1();                        // input + We complete
#pragma unroll
    for (int t = 0; t < 4; t++) FRAG_MMA(Ea, acc, t, 0);
    __syncthreads();
#pragma unroll
    for (int mt = 0; mt < 2; mt++)
#pragma unroll
        for (int hh = 0; hh < 2; hh++) {
            int lr = warp_m * 32 + mt * 16 + hh * 8 + qr;
#pragma unroll
            for (int nt2 = 0; nt2 < 4; nt2++) {
                int c = warp_n * 32 + nt2 * 8 + qc * 2;
                *(__half2*)(Eh + lr * 136 + c) = __floats2half2_rn(
                    gelu_t(acc[mt][nt2][hh * 2 + 0] + b_e[c]),
                    gelu_t(acc[mt][nt2][hh * 2 + 1] + b_e[c + 1]));
            }
        }

    // ===== Phase 2: Nh <- gelu(Nh @ Wn + center + b_n)  [S1] =====
    ZACC(acc);
    WPRE(WmE, 128, 0, 0, 0);
    WWAIT1();                        // Wn complete
#pragma unroll
    for (int t = 0; t < 4; t++) FRAG_MMA(Nh, acc, t, 1);
    __syncthreads();                 // all Nh reads done before overwrite
#pragma unroll
    for (int mt = 0; mt < 2; mt++)
#pragma unroll
        for (int hh = 0; hh < 2; hh++) {
            int lr = warp_m * 32 + mt * 16 + hh * 8 + qr;
            const float* cv = center + (long)((row0 + lr) >> 5) * 128;
#pragma unroll
            for (int nt2 = 0; nt2 < 4; nt2++) {
                int c = warp_n * 32 + nt2 * 8 + qc * 2;
                float2 ctr = *(const float2*)(cv + c);
                *(__half2*)(Nh + lr * 136 + c) = __floats2half2_rn(
                    gelu_t(acc[mt][nt2][hh * 2 + 0] + ctr.x + b_n[c]),
                    gelu_t(acc[mt][nt2][hh * 2 + 1] + ctr.y + b_n[c + 1]));
            }
        }

    // ===== Phase 3: Msg = gelu(Eh@WmE + Nh@WmN + b_m) -> Ea =====
    ZACC(acc);
    WPRE(WmN, 128, 0, 0, 1);
    WWAIT1();                        // WmE complete; also publishes Nh/Eh writes
#pragma unroll
    for (int t = 0; t < 4; t++) FRAG_MMA(Eh, acc, t, 0);
    __syncthreads();
    WPRE(Wq, 128, 0, 0, 0);
    WWAIT1();                        // WmN complete
#pragma unroll
    for (int t = 0; t < 4; t++) FRAG_MMA(Nh, acc, t, 1);
    __syncthreads();                 // all Ea(Msg src) reads? (Ea written below)
#pragma unroll
    for (int mt = 0; mt < 2; mt++)
#pragma unroll
        for (int hh = 0; hh < 2; hh++) {
            int lr = warp_m * 32 + mt * 16 + hh * 8 + qr;
#pragma unroll
            for (int nt2 = 0; nt2 < 4; nt2++) {
                int c = warp_n * 32 + nt2 * 8 + qc * 2;
                *(__half2*)(Ea + lr * 136 + c) = __floats2half2_rn(
                    gelu_t(acc[mt][nt2][hh * 2 + 0] + b_m[c]),
                    gelu_t(acc[mt][nt2][hh * 2 + 1] + b_m[c + 1]));
            }
        }

    // ===== Phase 4: qkv = Msg @ Wq + b_q  (3 column blocks of 128) =====
    // Wq cb0 in S0 (prefetched); chain cb1->S1, cb2->S0
    for (int cb = 0; cb < 3; cb++) {
        int S = cb & 1;
        ZACC(acc);
        if (cb + 1 < 3) {
            WPRE(Wq, 128, (cb + 1) * 128, 0, S ^ 1);
            WWAIT1();
        } else {
            WWAIT0();
        }
#pragma unroll
        for (int t = 0; t < 4; t++) FRAG_MMA(Ea, acc, t, S);
        __syncthreads();
#pragma unroll
        for (int mt = 0; mt < 2; mt++)
#pragma unroll
            for (int hh = 0; hh < 2; hh++) {
                int lr = warp_m * 32 + mt * 16 + hh * 8 + qr;
#pragma unroll
                for (int nt2 = 0; nt2 < 4; nt2++) {
                    int c = warp_n * 32 + nt2 * 8 + qc * 2;
                    *(__half2*)(qkv + (long)(row0 + lr) * 384 + cb * 128 + c) =
                        __floats2half2_rn(acc[mt][nt2][hh * 2 + 0] + b_q[cb * 128 + c],
                                          acc[mt][nt2][hh * 2 + 1] + b_q[cb * 128 + c + 1]);
                }
            }
    }
#undef ZACC
#undef FRAG_MMA
#undef WPRE
#undef WWAIT1
#undef WWAIT0
}

// ---------------- fused attention (R14-proven, 256 threads) -----------------------
#define FAT_SMEM 102400
__device__ __forceinline__ void cvt16(float* o, const __half* p) {
    uint4 a = *(const uint4*)p, b = *(const uint4*)(p + 8);
    const __half2* ha = (const __half2*)&a;
    const __half2* hb = (const __half2*)&b;
#pragma unroll
    for (int i = 0; i < 4; i++) {
        float2 f = __half22float2(ha[i]);
        o[i * 2] = f.x; o[i * 2 + 1] = f.y;
    }
#pragma unroll
    for (int i = 0; i < 4; i++) {
        float2 f = __half22float2(hb[i]);
        o[8 + i * 2] = f.x; o[8 + i * 2 + 1] = f.y;
    }
}

__global__ void __launch_bounds__(256) fused_attn(
    const __half* __restrict__ qkv, const __half* __restrict__ wout,
    const float* __restrict__ b_out, const int* __restrict__ num_valid,
    const float* __restrict__ edge_feat, const float* __restrict__ node_feat,
    float* __restrict__ out_edge, float* __restrict__ node1)
{
    extern __shared__ __half sh[];
    __half* qkvS = sh;                     // [64][384]
    __half* ctxS = sh + 24576;             // [64][136]
    __half* woutS = sh + 33280;            // [128][136]
    float*  sAgg  = (float*)(sh + 50688);  // [2][128]

    int tid = threadIdx.x;
    int n0 = blockIdx.x * 2;

    sAgg[tid] = 0.f;

    const uint4* src = (const uint4*)(qkv + (long)n0 * 32 * 384);
    uint4* dq = (uint4*)qkvS;
#pragma unroll
    for (int i = 0; i < 12; i++) dq[tid + i * 256] = src[tid + i * 256];

#pragma unroll
    for (int i = 0; i < 8; i++) {
        int c = tid + i * 256;
        int nn = c >> 4, k8 = c & 15;
        *(uint4*)(woutS + nn * 136 + k8 * 8) = *(const uint4*)(wout + nn * 128 + k8 * 8);
    }
    __syncthreads();

    int nv0 = num_valid[n0], nv1 = num_valid[n0 + 1];

    for (int it = tid; it < 512; it += 256) {
        int node = it >> 8;
        int head = (it >> 5) & 7;
        int q    = it & 31;
        int nv   = node ? nv1 : nv0;
        const __half* base = qkvS + (node * 32) * 384 + head * 16;
        float qv[16];
        cvt16(qv, base + q * 384);
        float s[32];
#pragma unroll
        for (int j = 0; j < 32; j++) {
            float kv[16];
            cvt16(kv, base + j * 384 + 128);
            float a = 0.f;
#pragma unroll
            for (int d = 0; d < 16; d++) a += qv[d] * kv[d];
            s[j] = a * 0.25f;
        }
        float m = -1e30f;
#pragma unroll
        for (int j = 0; j < 32; j++) if (j < nv && s[j] > m) m = s[j];
        float sum = 0.f;
#pragma unroll
        for (int j = 0; j < 32; j++) {
            float p = (j < nv) ? __expf(s[j] - m) : 0.f;
            s[j] = p; sum += p;
        }
        float inv = 1.f / sum;
        float ctx[16];
#pragma unroll
        for (int d = 0; d < 16; d++) ctx[d] = 0.f;
#pragma unroll
        for (int j = 0; j < 32; j++) {
            float p = s[j] * inv;
            float vv[16];
            cvt16(vv, base + j * 384 + 256);
#pragma unroll
            for (int d = 0; d < 16; d++) ctx[d] += p * vv[d];
        }
        uint4 o0, o1; __half2 h;
        h = __floats2half2_rn(ctx[0],  ctx[1]);  o0.x = *(uint32_t*)&h;
        h = __floats2half2_rn(ctx[2],  ctx[3]);  o0.y = *(uint32_t*)&h;
        h = __floats2half2_rn(ctx[4],  ctx[5]);  o0.z = *(uint32_t*)&h;
        h = __floats2half2_rn(ctx[6],  ctx[7]);  o0.w = *(uint32_t*)&h;
        h = __floats2half2_rn(ctx[8],  ctx[9]);  o1.x = *(uint32_t*)&h;
        h = __floats2half2_rn(ctx[10], ctx[11]); o1.y = *(uint32_t*)&h;
        h = __floats2half2_rn(ctx[12], ctx[13]); o1.z = *(uint32_t*)&h;
        h = __floats2half2_rn(ctx[14], ctx[15]); o1.w = *(uint32_t*)&h;
        __half* cd = ctxS + (node * 32 + q) * 136 + head * 16;
        *(uint4*)cd = o0;
        *(uint4*)(cd + 8) = o1;
    }
    __syncthreads();

    int lane = tid & 31, wid = tid >> 5;
    int warp_m = wid >> 2, warp_n = wid & 3;
    int qr = lane >> 2, qc = lane & 3;
    float acc[2][4][4];
#pragma unroll
    for (int i = 0; i < 2; i++)
#pragma unroll
        for (int j = 0; j < 4; j++)
#pragma unroll
            for (int c = 0; c < 4; c++) acc[i][j][c] = 0.f;

#pragma unroll
    for (int ks = 0; ks < 8; ks++) {
        int k16 = ks * 16;
        uint32_t af[2][4];
#pragma unroll
        for (int mt = 0; mt < 2; mt++) {
            const __half* p = ctxS + (warp_m * 32 + mt * 16 + qr) * 136 + k16 + qc * 2;
            af[mt][0] = *(const uint32_t*)(p);
            af[mt][1] = *(const uint32_t*)(p + 8 * 136);
            af[mt][2] = *(const uint32_t*)(p + 8);
            af[mt][3] = *(const uint32_t*)(p + 8 * 136 + 8);
        }
        uint32_t bf[4][2];
#pragma unroll
        for (int nt2 = 0; nt2 < 4; nt2++) {
            const __half* p = woutS + (warp_n * 32 + nt2 * 8 + qr) * 136 + k16 + qc * 2;
            bf[nt2][0] = *(const uint32_t*)(p);
            bf[nt2][1] = *(const uint32_t*)(p + 8);
        }
#pragma unroll
        for (int mt = 0; mt < 2; mt++)
#pragma unroll
            for (int nt2 = 0; nt2 < 4; nt2++) {
                asm volatile(
                    "mma.sync.aligned.m16n8k16.row.col.f32.f16.f16.f32 "
                    "{%0,%1,%2,%3}, {%4,%5,%6,%7}, {%8,%9}, {%0,%1,%2,%3};"
                    : "+f"(acc[mt][nt2][0]), "+f"(acc[mt][nt2][1]),
                      "+f"(acc[mt][nt2][2]), "+f"(acc[mt][nt2][3])
                    : "r"(af[mt][0]), "r"(af[mt][1]),
                      "r"(af[mt][2]), "r"(af[mt][3]),
                      "r"(bf[nt2][0]), "r"(bf[nt2][1]));
            }
    }

#pragma unroll
    for (int mt = 0; mt < 2; mt++) {
#pragma unroll
        for (int hh = 0; hh < 2; hh++) {
            int lr = warp_m * 32 + mt * 16 + hh * 8 + qr;
            int node = lr >> 5, kk = lr & 31;
            int nv = node ? nv1 : nv0;
            bool valid = kk < nv;
            long erow = ((long)(n0 + node) * 32 + kk) * 128;
#pragma unroll
            for (int nt2 = 0; nt2 < 4; nt2++) {
                int c = warp_n * 32 + nt2 * 8 + qc * 2;
                float v0 = acc[mt][nt2][hh * 2 + 0] + b_out[c];
                float v1 = acc[mt][nt2][hh * 2 + 1] + b_out[c + 1];
                float m0 = valid ? v0 : 0.f;
                float m1 = valid ? v1 : 0.f;
#pragma unroll
                for (int off = 4; off <= 16; off <<= 1) {
                    m0 += __shfl_xor_sync(0xffffffffu, m0, off);
                    m1 += __shfl_xor_sync(0xffffffffu, m1, off);
                }
                if (qr == 0) {
                    atomicAdd(&sAgg[node * 128 + c], m0);
                    atomicAdd(&sAgg[node * 128 + c + 1], m1);
                }
                float2 r2 = *(const float2*)(edge_feat + erow + c);
                *(float2*)(out_edge + erow + c) = make_float2(v0 + r2.x, v1 + r2.y);
            }
        }
    }
    __syncthreads();
    {
        int node = tid >> 7, c = tid & 127;
        long nidx = (long)(n0 + node) * 128 + c;
        node1[nidx] = sAgg[node * 128 + c] + node_feat[nidx];
    }
}

// ---------------- fused FFN (512 threads, double-buffered weight preload) ---------
#define FFN_SMEM 151552   // As 34816 + Hs 34816 + Wbuf 2*40960
__global__ void __launch_bounds__(512, 1) fused_ffn(
    const float* __restrict__ x, const float* __restrict__ gg, const float* __restrict__ bb,
    const __half* __restrict__ W1t, const float* __restrict__ b1,
    const __half* __restrict__ W2t, const float* __restrict__ b2,
    const float* __restrict__ resid, float* __restrict__ out, int Mtot)
{
    extern __shared__ __half shf[];
    __half* As = shf;
    __half* Hs = shf + 17408;
    uint32_t wb = (uint32_t)__cvta_generic_to_shared(shf + 34816);  // 2 x 40960 B

    int tid = threadIdx.x, lane = tid & 31, wid = tid >> 5;
    int row0 = blockIdx.x * 128;
    int warp_m = wid >> 2, warp_n = wid & 3;
    int qr = lane >> 2, qc = lane & 3;
    int kc = tid & 3, lrow = tid >> 2;

#define WPRE(Wp, kd, nbase, k0base, S) do {                                      \
        _Pragma("unroll")                                                        \
        for (int _s = 0; _s < 4; _s++)                                           \
            cp16(wb + (S) * 40960 + _s * 10240 + lrow * 80 + kc * 16,            \
                 (Wp) + (long)((nbase) + lrow) * (kd) + (k0base) + _s * 32 + kc * 8, 16); \
        asm volatile("cp.async.commit_group;" ::: "memory");                     \
    } while (0)

    // prefetch chain: W1[0](S0), W2[k0](S1), W1[1](S0), W2[k128](S1)
    WPRE(W1t, 128, 0, 0, 0);

    for (int r = wid; r < 128; r += 16) {
        int gr = row0 + r;
        uint2 pk = make_uint2(0u, 0u);
        if (gr < Mtot) {
            float4 v = *(const float4*)(x + (long)gr * 128 + lane * 4);
            float s  = v.x + v.y + v.z + v.w;
            float s2 = v.x*v.x + v.y*v.y + v.z*v.z + v.w*v.w;
#pragma unroll
            for (int o = 16; o; o >>= 1) {
                s  += __shfl_xor_sync(0xffffffffu, s,  o);
                s2 += __shfl_xor_sync(0xffffffffu, s2, o);
            }
            float mean = s * (1.f / 128.f);
            float var  = s2 * (1.f / 128.f) - mean * mean;
            float rs = rsqrtf(var + 1e-5f);
            float4 gv = *(const float4*)(gg + lane * 4);
            float4 bv = *(const float4*)(bb + lane * 4);
            __half2 h0 = __floats2half2_rn((v.x - mean) * rs * gv.x + bv.x,
                                           (v.y - mean) * rs * gv.y + bv.y);
            __half2 h1 = __floats2half2_rn((v.z - mean) * rs * gv.z + bv.z,
                                           (v.w - mean) * rs * gv.w + bv.w);
            pk = make_uint2(*(uint32_t*)&h0, *(uint32_t*)&h1);
        }
        *(uint2*)(As + r * 136 + lane * 4) = pk;
    }

#define FRAG_MMA(Abase, ACC, T, S) do {                                          \
        const __half* _Ws = (const __half*)(shf + 34816) + (S) * 20480           \
                            + (T) * 5120 + (warp_n * 32) * 40;                   \
        _Pragma("unroll")                                                        \
        for (int ks = 0; ks < 2; ks++) {                                         \
            int k16 = (T) * 32 + ks * 16;                                        \
            uint32_t af[2][4];                                                   \
            _Pragma("unroll")                                                    \
            for (int mt = 0; mt < 2; mt++) {                                     \
                const __half* p = (Abase) + (warp_m * 32 + mt * 16 + qr) * 136   \
                                  + k16 + qc * 2;                                \
                af[mt][0] = *(const uint32_t*)(p);                               \
                af[mt][1] = *(const uint32_t*)(p + 8 * 136);                     \
                af[mt][2] = *(const uint32_t*)(p + 8);                           \
                af[mt][3] = *(const uint32_t*)(p + 8 * 136 + 8);                 \
            }                                                                    \
            uint32_t bf[4][2];                                                   \
            _Pragma("unroll")                                                    \
            for (int nt2 = 0; nt2 < 4; nt2++) {                                  \
                const __half* p = _Ws + (nt2 * 8 + qr) * 40 + ks * 16 + qc * 2;  \
                bf[nt2][0] = *(const uint32_t*)(p);                              \
                bf[nt2][1] = *(const uint32_t*)(p + 8);                          \
            }                                                                    \
            _Pragma("unroll")                                                    \
            for (int mt = 0; mt < 2; mt++)                                       \
                _Pragma("unroll")                                                \
                for (int nt2 = 0; nt2 < 4; nt2++) {                              \
                    asm volatile(                                                \
                        "mma.sync.aligned.m16n8k16.row.col.f32.f16.f16.f32 "     \
                        "{%0,%1,%2,%3}, {%4,%5,%6,%7}, {%8,%9}, {%0,%1,%2,%3};"  \
                        : "+f"((ACC)[mt][nt2][0]), "+f"((ACC)[mt][nt2][1]),      \
                          "+f"((ACC)[mt][nt2][2]), "+f"((ACC)[mt][nt2][3])       \
                        : "r"(af[mt][0]), "r"(af[mt][1]),                        \
                          "r"(af[mt][2]), "r"(af[mt][3]),                        \
                          "r"(bf[nt2][0]), "r"(bf[nt2][1]));                     \
                }                                                                \
        }                                                                        \
    } while (0)

    float acc2[2][4][4];
#pragma unroll
    for (int i = 0; i < 2; i++)
#pragma unroll
        for (int j = 0; j < 4; j++)
#pragma unroll
            for (int c = 0; c < 4; c++) acc2[i][j][c] = 0.f;

    for (int nh = 0; nh < 2; nh++) {
        // ---- GEMM1: Hs = gelu(As @ W1t[nh-half] + b1)  [S0] ----
        float acc1[2][4][4];
#pragma unroll
        for (int i = 0; i < 2; i++)
#pragma unroll
            for (int j = 0; j < 4; j++)
#pragma unroll
                for (int c = 0; c < 4; c++) acc1[i][j][c] = 0.f;

        WPRE(W2t, 256, 0, nh * 128, 1);     // prefetch next
        asm volatile("cp.async.wait_group 1;" ::: "memory");
        __syncthreads();                    // W1 ready; publishes As/Hs writes
#pragma unroll
        for (int t = 0; t < 4; t++) FRAG_MMA(As, acc1, t, 0);
        __syncthreads();
#pragma unroll
        for (int mt = 0; mt < 2; mt++) {
#pragma unroll
            for (int hh = 0; hh < 2; hh++) {
                int lr = warp_m * 32 + mt * 16 + hh * 8 + qr;
#pragma unroll
                for (int nt2 = 0; nt2 < 4; nt2++) {
                    int c = warp_n * 32 + nt2 * 8 + qc * 2;
                    float v0 = gelu_t(acc1[mt][nt2][hh * 2 + 0] + b1[nh * 128 + c]);
                    float v1 = gelu_t(acc1[mt][nt2][hh * 2 + 1] + b1[nh * 128 + c + 1]);
                    *(__half2*)(Hs + lr * 136 + c) = __floats2half2_rn(v0, v1);
                }
            }
        }

        // ---- GEMM2 partial-K: acc2 += Hs @ W2t[:, nh*128..]  [S1] ----
        if (nh == 0) WPRE(W1t, 128, 128, 0, 0);   // prefetch W1[1]
        asm volatile("cp.async.wait_group %0;" :: "n"(0) : "memory");
        // (nh==0: W1[1] pending would be group-1; use wait 1 when prefetched)
        __syncthreads();
#pragma unroll
        for (int t = 0; t < 4; t++) FRAG_MMA(Hs, acc2, t, 1);
        __syncthreads();
    }
#undef FRAG_MMA
#undef WPRE

#pragma unroll
    for (int mt = 0; mt < 2; mt++) {
#pragma unroll
        for (int hh = 0; hh < 2; hh++) {
            int gr = row0 + warp_m * 32 + mt * 16 + hh * 8 + qr;
            if (gr >= Mtot) continue;
#pragma unroll
            for (int nt2 = 0; nt2 < 4; nt2++) {
                int c = warp_n * 32 + nt2 * 8 + qc * 2;
                float v0 = acc2[mt][nt2][hh * 2 + 0] + b2[c];
                float v1 = acc2[mt][nt2][hh * 2 + 1] + b2[c + 1];
                long oidx = (long)gr * 128 + c;
                float2 r2 = *(const float2*)(resid + oidx);
                *(float2*)(out + oidx) = make_float2(v0 + r2.x, v1 + r2.y);
            }
        }
    }
}

// ---------------- driver -----------------------------------------------------------
static void launch_gemm(const __half* A, int kdA, const __half* A2, int kdA2,
                        const __half* Wt, const __half* Wt2, const float* bias,
                        const int* gather, const float* rowvec, int rowdiv,
                        const float* resid, void* out, float* out2,
                        int M, int ncols, int flags)
{
    dim3 g((M + 127) / 128, ncols / 128);
    gemm_h<<<g, 256, GEMM_SMEM>>>(A, kdA, A2, kdA2, Wt, Wt2, bias, gather,
                                  rowvec, rowdiv, resid, out, out2, M, ncols, flags);
}
static void launch_T(const float* src, __half* dst, int K, int N) {
    dim3 g((N + 31) / 32, (K + 31) / 32);
    transpose_half<<<g, 256>>>(src, dst, K, N);
}
static void launch_half(const float* src, __half* dst, long n) {
    long n4 = n / 4;
    half_kernel<<<(unsigned)((n4 + 255) / 256), 256>>>(src, dst, n4);
}
static void launch_ln(const float* x, const float* g, const float* b,
                      void* y, int mode, int nrows) {
    ln_kernel<<<(nrows + 7) / 8, 256>>>(x, g, b, y, mode, nrows);
}

extern "C" void kernel_launch(void* const* d_in, const int* in_sizes, int n_in,
                              void* d_out, int out_size)
{
    const float* node_features = (const float*)d_in[0];
    const float* edge_features = (const float*)d_in[1];
    const float* edge_attr     = (const float*)d_in[2];
    const int*   neighbor_list = (const int*)d_in[3];
    const int*   num_valid     = (const int*)d_in[4];
    const float* W_edge = (const float*)d_in[5];
    const float* b_edge = (const float*)d_in[6];
    const float* W_node = (const float*)d_in[7];
    const float* b_node = (const float*)d_in[8];
    const float* W_msg  = (const float*)d_in[9];
    const float* b_msg  = (const float*)d_in[10];
    const float* W_qkv  = (const float*)d_in[11];
    const float* b_qkv  = (const float*)d_in[12];
    const float* W_out  = (const float*)d_in[13];
    const float* b_out  = (const float*)d_in[14];
    const float* g_attn = (const float*)d_in[15];
    const float* be_attn= (const float*)d_in[16];
    const float* g_fn   = (const float*)d_in[17];
    const float* be_fn  = (const float*)d_in[18];
    const float* g_fe   = (const float*)d_in[19];
    const float* be_fe  = (const float*)d_in[20];
    const float* Wn1 = (const float*)d_in[21];
    const float* bn1 = (const float*)d_in[22];
    const float* Wn2 = (const float*)d_in[23];
    const float* bn2 = (const float*)d_in[24];
    const float* We1 = (const float*)d_in[25];
    const float* be1 = (const float*)d_in[26];
    const float* We2 = (const float*)d_in[27];
    const float* be2 = (const float*)d_in[28];

    float *s_nh, *s_c, *s_nf1, *s_big, *s_w;
    cudaGetSymbolAddress((void**)&s_nh,  S_nh);
    cudaGetSymbolAddress((void**)&s_c,   S_c);
    cudaGetSymbolAddress((void**)&s_nf1, S_nf1);
    cudaGetSymbolAddress((void**)&s_big, S_big);
    cudaGetSymbolAddress((void**)&s_w,   S_w);

    cudaFuncSetAttribute(fused_attn, cudaFuncAttributeMaxDynamicSharedMemorySize, FAT_SMEM);
    cudaFuncSetAttribute(fused_ffn,  cudaFuncAttributeMaxDynamicSharedMemorySize, FFN_SMEM);
    cudaFuncSetAttribute(fused_msg,  cudaFuncAttributeMaxDynamicSharedMemorySize, MSG_SMEM);

    float* out_node = (float*)d_out;
    float* out_edge = out_node + (long)N_ * H_;

    __half* h_nh  = (__half*)s_nh;
    __half* h_ea  = (__half*)(s_big + (long)M_ * 192);  // upper half of S_big
    __half* h_qkv = (__half*)s_big;

    __half* wbase = (__half*)s_w;
    __half* tW_edge  = wbase;
    __half* tW_nodeC = wbase + 16384;
    __half* tW_nodeN = wbase + 32768;
    __half* tW_msgE  = wbase + 49152;
    __half* tW_msgN  = wbase + 65536;
    __half* tW_qkv   = wbase + 81920;
    __half* tW_out   = wbase + 131072;
    __half* tWn1     = wbase + 147456;
    __half* tWn2     = wbase + 180224;
    __half* tWe1     = wbase + 212992;
    __half* tWe2     = wbase + 245760;

    // 0) transpose+halve weights; halve edge_attr (into upper half of S_big)
    launch_T(W_edge,            tW_edge,  128, 128);
    launch_T(W_node,            tW_nodeC, 128, 128);
    launch_T(W_node + 128*128,  tW_nodeN, 128, 128);
    launch_T(W_msg,             tW_msgE,  128, 128);
    launch_T(W_msg + 128*128,   tW_msgN,  128, 128);
    launch_T(W_qkv,             tW_qkv,   128, 384);
    launch_T(W_out,             tW_out,   128, 128);
    launch_T(Wn1,               tWn1,     128, 256);
    launch_T(Wn2,               tWn2,     256, 128);
    launch_T(We1,               tWe1,     128, 256);
    launch_T(We2,               tWe2,     256, 128);
    launch_half(edge_attr, h_ea, (long)M_ * 128);

    // 1) node_hidden = LN(node_features) -> f16
    launch_ln(node_features, g_attn, be_attn, h_nh, 1, N_);
    // 2) center proj -> f32
    launch_gemm(h_nh, 128, nullptr, 0, tW_nodeC, nullptr, nullptr,
                nullptr, nullptr, 1, nullptr, s_c, nullptr, N_, 128, 0);
    // 3) fused edge chain: eh/node_hid/msg/qkv -> h_qkv (lower S_big)
    fused_msg<<<M_ / 128, 512, MSG_SMEM>>>(
        h_ea, h_nh, s_c, neighbor_list,
        tW_edge, b_edge, tW_nodeN, b_node,
        tW_msgE, tW_msgN, b_msg, tW_qkv, b_qkv, h_qkv);
    // 4) fused: attention + out-proj + edge residual + masked aggregation
    fused_attn<<<N_ / 2, 256, FAT_SMEM>>>(h_qkv, tW_out, b_out, num_valid,
                                          edge_features, node_features,
                                          out_edge, s_nf1);
    // 5) node FFN (fused)
    fused_ffn<<<(N_ + 127) / 128, 512, FFN_SMEM>>>(
        s_nf1, g_fn, be_fn, tWn1, bn1, tWn2, bn2, s_nf1, out_node, N_);
    // 6) edge FFN (fused; in-place over out_edge)
    fused_ffn<<<(M_ + 127) / 128, 512, FFN_SMEM>>>(
        out_edge, g_fe, be_fe, tWe1, be1, tWe2, be2, out_edge, out_edge, M_);
}